// round 11
// baseline (speedup 1.0000x reference)
#include <cuda_runtime.h>
#include <cuda_bf16.h>

#define EPS 1e-5f
#define LN3 1.0986122886681098f

// ---- static scratch ----
__device__ __align__(16) float4 g_wt[1 << 19];   // per-row softmax weights
__device__ int g_flag[4096];                     // per-256-row-chunk ready flags

__device__ __forceinline__ float tanh_approx(float v) {
    float r;
    asm("tanh.approx.f32 %0, %1;" : "=f"(r) : "f"(v));
    return r;
}

__device__ __forceinline__ unsigned long long ffma2(
    unsigned long long a, unsigned long long b, unsigned long long c)
{
    unsigned long long d;
    asm("fma.rn.f32x2 %0, %1, %2, %3;" : "=l"(d) : "l"(a), "l"(b), "l"(c));
    return d;
}

// One kernel, two roles. Per 40-block tile: 32 stream + 8 mlp blocks.
// Both roles fit <=~80 regs -> 3 blocks/SM -> ~19 stream warps/SM.
__global__ __launch_bounds__(256, 3) void pc_kernel(
    const float* __restrict__ x, const float* __restrict__ mask,
    const float* __restrict__ attn_w, const float* __restrict__ attn_b,
    const float* __restrict__ w1, const float* __restrict__ b1,
    const float* __restrict__ g1, const float* __restrict__ be1,
    const float* __restrict__ m1, const float* __restrict__ v1,
    const float* __restrict__ w2, const float* __restrict__ b2,
    const float* __restrict__ g2, const float* __restrict__ be2,
    const float* __restrict__ m2, const float* __restrict__ v2,
    const float* __restrict__ w3, const float* __restrict__ b3,
    float* __restrict__ out, int B, int write_weight, int write_cls,
    int nStreamBlocks, int nTasks, int nMlpWarps)
{
    __shared__ float4 s_M4[128 * 16];   // 32KB (mlp role)
    __shared__ float4 s_w1p[128];
    __shared__ float  s_b1[128];
    __shared__ float  s_q[64], s_e[64], s_ct[64];
    __shared__ float  s_a1[128], s_c1[128];
    __shared__ float  s_C;
    __shared__ float4 s_aw[64];         // (stream role)
    __shared__ float  s_ab;

    const int tid  = threadIdx.x;
    const int lane = tid & 31;
    const int warp = tid >> 5;
    const unsigned FULL = 0xFFFFFFFFu;

    const int tile = blockIdx.x / 40;
    const int pos  = blockIdx.x % 40;

    if (pos < 32) {
        // ======================= STREAM ROLE (single-row) =======================
        const int s = tile * 32 + pos;
        if (s >= nStreamBlocks) return;

        for (int i = tid; i < 64; i += 256) s_aw[i] = ((const float4*)attn_w)[i];
        if (tid == 0) s_ab = attn_b[0];
        __syncthreads();

        const float4 wa = s_aw[lane], wb = s_aw[32 + lane];
        const float ab = s_ab;
        const long long base = (long long)s * 256 + warp * 32;

        for (int r = 0; r < 32; r++) {
            const long long b = base + r;
            if (b >= B) break;
            const float4 mk = __ldg(((const float4*)mask) + b);
            const float4* xr = (const float4*)(x + b * 1024);
            float4 xa0 = xr[lane],       xb0 = xr[32 + lane];
            float4 xa1 = xr[64 + lane],  xb1 = xr[96 + lane];
            float4 xa2 = xr[128 + lane], xb2 = xr[160 + lane];
            float4 xa3 = xr[192 + lane], xb3 = xr[224 + lane];

            float s0 = xa0.x*wa.x + xa0.y*wa.y + xa0.z*wa.z + xa0.w*wa.w
                     + xb0.x*wb.x + xb0.y*wb.y + xb0.z*wb.z + xb0.w*wb.w;
            float s1 = xa1.x*wa.x + xa1.y*wa.y + xa1.z*wa.z + xa1.w*wa.w
                     + xb1.x*wb.x + xb1.y*wb.y + xb1.z*wb.z + xb1.w*wb.w;
            float s2 = xa2.x*wa.x + xa2.y*wa.y + xa2.z*wa.z + xa2.w*wa.w
                     + xb2.x*wb.x + xb2.y*wb.y + xb2.z*wb.z + xb2.w*wb.w;
            float s3 = xa3.x*wa.x + xa3.y*wa.y + xa3.z*wa.z + xa3.w*wa.w
                     + xb3.x*wb.x + xb3.y*wb.y + xb3.z*wb.z + xb3.w*wb.w;
            #pragma unroll
            for (int o = 16; o; o >>= 1) {
                s0 += __shfl_xor_sync(FULL, s0, o);
                s1 += __shfl_xor_sync(FULL, s1, o);
                s2 += __shfl_xor_sync(FULL, s2, o);
                s3 += __shfl_xor_sync(FULL, s3, o);
            }

            float t0 = tanh_approx(s0 + ab) + mk.x;
            float t1 = tanh_approx(s1 + ab) + mk.y;
            float t2 = tanh_approx(s2 + ab) + mk.z;
            float t3 = tanh_approx(s3 + ab) + mk.w;

            float mx = fmaxf(fmaxf(t0, t1), fmaxf(t2, t3));
            float e0 = __expf(t0 - mx), e1 = __expf(t1 - mx);
            float e2 = __expf(t2 - mx), e3 = __expf(t3 - mx);
            float inv = 1.0f / (e0 + e1 + e2 + e3);
            float wt0 = e0 * inv, wt1 = e1 * inv, wt2 = e2 * inv, wt3 = e3 * inv;

            float4 pa, pb;
            pa.x = wt0*xa0.x + wt1*xa1.x + wt2*xa2.x + wt3*xa3.x;
            pa.y = wt0*xa0.y + wt1*xa1.y + wt2*xa2.y + wt3*xa3.y;
            pa.z = wt0*xa0.z + wt1*xa1.z + wt2*xa2.z + wt3*xa3.z;
            pa.w = wt0*xa0.w + wt1*xa1.w + wt2*xa2.w + wt3*xa3.w;
            pb.x = wt0*xb0.x + wt1*xb1.x + wt2*xb2.x + wt3*xb3.x;
            pb.y = wt0*xb0.y + wt1*xb1.y + wt2*xb2.y + wt3*xb3.y;
            pb.z = wt0*xb0.z + wt1*xb1.z + wt2*xb2.z + wt3*xb3.z;
            pb.w = wt0*xb0.w + wt1*xb1.w + wt2*xb2.w + wt3*xb3.w;

            float4* orow = (float4*)(out + (size_t)b * 256);
            orow[lane]      = pa;
            orow[32 + lane] = pb;

            if (lane == 0) {
                float4 wv = make_float4(wt0, wt1, wt2, wt3);
                g_wt[b] = wv;
                if (write_weight)
                    *(float4*)(out + (size_t)B * 256 + (size_t)b * 4) = wv;
            }
        }
        __syncthreads();             // all 256 rows of this chunk written
        if (tid == 0) {
            __threadfence();         // release
            atomicExch(&g_flag[s], 1);
        }
        return;
    }

    // ======================= MLP ROLE (R=2 rows/lane, C=4 j-chunks) =======================
    const int mb = tile * 8 + (pos - 32);

    // ---- fold all classifier constants in-block ----
    for (int i = tid; i < 128; i += 256) {
        float a = g1[i] * rsqrtf(v1[i] + EPS);
        s_a1[i] = a; s_c1[i] = be1[i] - a * m1[i]; s_b1[i] = b1[i];
        s_w1p[i] = make_float4(w1[i*4], w1[i*4+1], w1[i*4+2], w1[i*4+3]);
    }
    __syncthreads();
    float* s_M = (float*)s_M4;
    for (int i = tid; i < 8192; i += 256) {
        int j = i >> 7, k = i & 127;
        s_M[k * 64 + j] = w2[j * 128 + k] * s_a1[k];
    }
    if (tid < 64) {
        float acc = b2[tid];
        #pragma unroll 8
        for (int k = 0; k < 128; k++) acc += w2[tid * 128 + k] * s_c1[k];
        s_q[tid] = acc;
        float a2 = g2[tid] * rsqrtf(v2[tid] + EPS);
        float wd = w3[64 + tid] - w3[tid];
        s_e[tid] = wd * a2;
        s_ct[tid] = wd * (be2[tid] - a2 * m2[tid]);
    }
    __syncthreads();
    if (tid == 0) {
        float C = b3[1] - b3[0];
        #pragma unroll 8
        for (int j = 0; j < 64; j++) C += s_ct[j];
        s_C = C;
    }
    __syncthreads();

    const float Cc = s_C;
    const int mwarp = mb * 8 + warp;

    for (int t = mwarp; t < nTasks; t += nMlpWarps) {
        // ---- wait for producer chunk (task = 64 rows; chunk = 256 rows) ----
        if (lane == 0) {
            while (atomicAdd(&g_flag[t >> 2], 0) == 0) __nanosleep(128);
        }
        __syncwarp();
        __threadfence();             // acquire

        const long long base = (long long)t << 6;   // 64 rows per task

        bool  valid[2];
        float4 wt[2];
        #pragma unroll
        for (int r = 0; r < 2; r++) {
            long long row = base + 32 * r + lane;
            valid[r] = (row < B);
            wt[r] = valid[r] ? g_wt[row] : make_float4(1.f, 0.f, 0.f, 0.f);
        }

        float dec[2] = {Cc, Cc};

        #pragma unroll
        for (int c = 0; c < 4; c++) {         // j-chunks of 16 outputs
            unsigned long long acc[2][8];
            #pragma unroll
            for (int r = 0; r < 2; r++)
                #pragma unroll
                for (int p = 0; p < 8; p++) acc[r][p] = 0ull;

            #pragma unroll 2
            for (int k = 0; k < 128; k++) {
                float4 wp = s_w1p[k];
                float bb = s_b1[k];
                unsigned long long vv[2];
                #pragma unroll
                for (int r = 0; r < 2; r++) {
                    float z = fmaf(wt[r].x, wp.x, fmaf(wt[r].y, wp.y,
                              fmaf(wt[r].z, wp.z, fmaf(wt[r].w, wp.w, bb))));
                    float v = fmaxf(z, 0.0f);
                    asm("mov.b64 %0, {%1, %1};" : "=l"(vv[r]) : "f"(v));
                }
                const ulonglong2* row = (const ulonglong2*)s_M4 + k * 16 + c * 4;
                #pragma unroll
                for (int tt = 0; tt < 4; tt++) {
                    ulonglong2 m = row[tt];
                    #pragma unroll
                    for (int r = 0; r < 2; r++) {
                        acc[r][2 * tt]     = ffma2(m.x, vv[r], acc[r][2 * tt]);
                        acc[r][2 * tt + 1] = ffma2(m.y, vv[r], acc[r][2 * tt + 1]);
                    }
                }
            }
            #pragma unroll
            for (int p = 0; p < 8; p++) {
                const int j = c * 16 + 2 * p;
                const float q0 = s_q[j], q1 = s_q[j + 1];
                const float e0 = s_e[j], e1 = s_e[j + 1];
                #pragma unroll
                for (int r = 0; r < 2; r++) {
                    float z0 = __uint_as_float((unsigned)(acc[r][p] & 0xFFFFFFFFull)) + q0;
                    float z1 = __uint_as_float((unsigned)(acc[r][p] >> 32))           + q1;
                    dec[r] = fmaf(e0, fmaxf(z0, 0.0f), dec[r]);
                    dec[r] = fmaf(e1, fmaxf(z1, 0.0f), dec[r]);
                }
            }
        }

        // ---- per r-set: cls write + rare argmax-gather overwrite ----
        #pragma unroll
        for (int r = 0; r < 2; r++) {
            int mi = 0; float bm = wt[r].x;
            if (wt[r].y > bm) { bm = wt[r].y; mi = 1; }
            if (wt[r].z > bm) { bm = wt[r].z; mi = 2; }
            if (wt[r].w > bm) { bm = wt[r].w; mi = 3; }

            const bool cls1 = valid[r] && (dec[r] > LN3);
            const long long rbase = base + 32 * r;
            unsigned mbits = __ballot_sync(FULL, cls1);
            while (mbits) {
                const int rr = __ffs(mbits) - 1;
                mbits &= mbits - 1;
                const long long b = rbase + rr;
                const int gmi = __shfl_sync(FULL, mi, rr);
                const float4* gsrc = (const float4*)(x + b * 1024 + (size_t)gmi * 256);
                float4 v0 = gsrc[lane], v1 = gsrc[32 + lane];
                float4* orow = (float4*)(out + (size_t)b * 256);
                orow[lane]      = v0;
                orow[32 + lane] = v1;
            }
            if (write_cls && valid[r])
                out[(size_t)B * 260 + rbase + lane] = cls1 ? 1.0f : 0.0f;
        }
    }
}

extern "C" void kernel_launch(void* const* d_in, const int* in_sizes, int n_in,
                              void* d_out, int out_size)
{
    const float* x      = (const float*)d_in[0];
    const float* mask   = (const float*)d_in[1];
    const float* attn_w = (const float*)d_in[2];
    const float* attn_b = (const float*)d_in[3];
    const float* w1     = (const float*)d_in[4];
    const float* b1     = (const float*)d_in[5];
    const float* g1     = (const float*)d_in[6];
    const float* be1    = (const float*)d_in[7];
    const float* m1     = (const float*)d_in[8];
    const float* v1     = (const float*)d_in[9];
    const float* w2     = (const float*)d_in[10];
    const float* b2     = (const float*)d_in[11];
    const float* g2     = (const float*)d_in[12];
    const float* be2    = (const float*)d_in[13];
    const float* m2     = (const float*)d_in[14];
    const float* v2     = (const float*)d_in[15];
    const float* w3     = (const float*)d_in[16];
    const float* b3     = (const float*)d_in[17];
    float* out = (float*)d_out;

    const int B = in_sizes[0] / 1024;   // x = [B,4,256]
    const long long need_w = (long long)B * 260;
    const long long need_c = (long long)B * 261;
    const int write_weight = ((long long)out_size >= need_w) ? 1 : 0;
    const int write_cls    = ((long long)out_size >= need_c) ? 1 : 0;

    const int nStreamBlocks = (B + 255) >> 8;       // 256-row chunks
    const int nTasks        = (B + 63) >> 6;        // 64-row mlp tasks
    const int tiles         = (nStreamBlocks + 31) >> 5;
    const int grid          = tiles * 40;           // 32 stream + 8 mlp per tile
    const int nMlpWarps     = tiles * 8 * 8;

    void* flagPtr = nullptr;
    cudaGetSymbolAddress(&flagPtr, g_flag);
    cudaMemsetAsync(flagPtr, 0, sizeof(int) * 4096);

    pc_kernel<<<grid, 256>>>(x, mask, attn_w, attn_b,
                             w1, b1, g1, be1, m1, v1,
                             w2, b2, g2, be2, m2, v2, w3, b3,
                             out, B, write_weight, write_cls,
                             nStreamBlocks, nTasks, nMlpWarps);
}